// round 15
// baseline (speedup 1.0000x reference)
#include <cuda_runtime.h>
#include <cuda_fp16.h>
#include <math.h>
#include <stdint.h>

#define BB 4
#define SS 2048
#define DD 1024
#define HH 16
#define HDIM 64

#define SCALE_L2E 0.18033688011112042f   // 0.125 * log2(e)

// fp16 scratch (device globals: allocation-free per harness rules)
__device__ __half g_h16[BB * SS * DD];
__device__ __half g_wa16[DD * 3 * DD];    // Q-columns pre-scaled by SCALE_L2E
__device__ __half g_wp16[DD * DD];
__device__ __half g_qkv16[BB * SS * 3 * DD];
__device__ __half g_ctx16[BB * SS * DD];
__device__ float  g_ba[3 * DD];           // scaled copy of b_attn

// ---------------------------------------------------------------------------
// helpers
// ---------------------------------------------------------------------------
__device__ __forceinline__ uint32_t smem_u32(const void* p) {
    uint32_t a;
    asm("{ .reg .u64 t; cvta.to.shared.u64 t, %1; cvt.u32.u64 %0, t; }"
        : "=r"(a) : "l"(p));
    return a;
}

__device__ __forceinline__ void cpa16(uint32_t dst, const void* src) {
    asm volatile("cp.async.ca.shared.global [%0], [%1], 16;"
                 :: "r"(dst), "l"(src));
}
#define CP_COMMIT() asm volatile("cp.async.commit_group;")
#define CP_WAIT(n)  asm volatile("cp.async.wait_group %0;" :: "n"(n))

__device__ __forceinline__ void ldsm_x4(uint32_t* d, uint32_t addr) {
    asm volatile("ldmatrix.sync.aligned.m8n8.x4.shared.b16 {%0,%1,%2,%3}, [%4];"
                 : "=r"(d[0]), "=r"(d[1]), "=r"(d[2]), "=r"(d[3]) : "r"(addr));
}
__device__ __forceinline__ void ldsm_x4t(uint32_t* d, uint32_t addr) {
    asm volatile("ldmatrix.sync.aligned.m8n8.x4.trans.shared.b16 {%0,%1,%2,%3}, [%4];"
                 : "=r"(d[0]), "=r"(d[1]), "=r"(d[2]), "=r"(d[3]) : "r"(addr));
}

__device__ __forceinline__ void mma_f16(float* c, const uint32_t* a,
                                        uint32_t b0, uint32_t b1) {
    asm volatile(
        "mma.sync.aligned.m16n8k16.row.col.f32.f16.f16.f32 "
        "{%0,%1,%2,%3}, {%4,%5,%6,%7}, {%8,%9}, {%0,%1,%2,%3};"
        : "+f"(c[0]), "+f"(c[1]), "+f"(c[2]), "+f"(c[3])
        : "r"(a[0]), "r"(a[1]), "r"(a[2]), "r"(a[3]), "r"(b0), "r"(b1));
}

__device__ __forceinline__ uint32_t h2bits(float x, float y) {
    __half2 h = __floats2half2_rn(x, y);
    return *reinterpret_cast<uint32_t*>(&h);
}

// hardware exp2 (MUFU.EX2) — guaranteed single-instruction regardless of
// compiler fast-math settings.
__device__ __forceinline__ float ex2(float x) {
    float r;
    asm("ex2.approx.ftz.f32 %0, %1;" : "=f"(r) : "f"(x));
    return r;
}

// ---------------------------------------------------------------------------
// conversion kernels
// ---------------------------------------------------------------------------
#define N4_WA (DD * 3 * DD / 4)
#define N4_WP (DD * DD / 4)
#define N4_W  (N4_WA + N4_WP)
#define N4_HB (SS * DD / 4)     // one batch of hidden

__global__ void conv_weights(const float4* __restrict__ s_wa,
                             const float4* __restrict__ s_wp,
                             const float* __restrict__ b_attn,
                             uint2* __restrict__ d_wa,
                             uint2* __restrict__ d_wp)
{
    int i0 = blockIdx.x * blockDim.x + threadIdx.x;
    if (i0 < 3 * DD)
        g_ba[i0] = b_attn[i0] * ((i0 < DD) ? SCALE_L2E : 1.0f);

    const int stride = gridDim.x * blockDim.x;
    for (int i = i0; i < N4_W; i += stride) {
        if (i < N4_WA) {
            float4 v = s_wa[i];
            float s = (((i * 4) % (3 * DD)) < DD) ? SCALE_L2E : 1.0f;
            uint2 u;
            u.x = h2bits(v.x * s, v.y * s);
            u.y = h2bits(v.z * s, v.w * s);
            d_wa[i] = u;
        } else {
            int idx = i - N4_WA;
            float4 v = s_wp[idx];
            uint2 u;
            u.x = h2bits(v.x, v.y);
            u.y = h2bits(v.z, v.w);
            d_wp[idx] = u;
        }
    }
}

__global__ void conv_hidden(const float4* __restrict__ src,
                            uint2* __restrict__ dst)
{
    int i = blockIdx.x * blockDim.x + threadIdx.x;
    const int stride = gridDim.x * blockDim.x;
    for (; i < N4_HB; i += stride) {
        float4 v = src[i];
        uint2 u;
        u.x = h2bits(v.x, v.y);
        u.y = h2bits(v.z, v.w);
        dst[i] = u;
    }
}

// ---------------------------------------------------------------------------
// fp16 GEMM v5 (R11 winner): CTA 128x128, BK=32, 8 warps, warp 32x64,
// 4-stage cp.async ring, ONE __syncthreads per epoch.
// ---------------------------------------------------------------------------
#define LDAH 40
#define LDBH 136
#define ASTG_B (128 * LDAH * 2)
#define BSTG_B (32 * LDBH * 2)
#define STG_B  (ASTG_B + BSTG_B)
#define GSMEM_TOTAL (4 * STG_B)

template<int OUT16>
__global__ __launch_bounds__(256, 2)
void gemm_f16_v5(const __half* __restrict__ A, const __half* __restrict__ W,
                 const float* __restrict__ bias, void* __restrict__ Cout,
                 int M, int N, int K)
{
    extern __shared__ char gsm[];

    const int tid  = threadIdx.x;
    const int warp = tid >> 5;
    const int lane = tid & 31;
    const int gid  = lane >> 2;
    const int tig  = lane & 3;
    const int wm = warp >> 1;
    const int wn = warp & 1;

    const int row0 = blockIdx.y * 128;
    const int col0 = blockIdx.x * 128;

    float acc[2][8][4];
    #pragma unroll
    for (int a = 0; a < 2; a++)
        #pragma unroll
        for (int j = 0; j < 8; j++)
            #pragma unroll
            for (int v = 0; v < 4; v++) acc[a][j][v] = 0.f;

    #define GSTAGE(BUF, KT)                                                   \
        do {                                                                  \
            __half* Asb = (__half*)(gsm + (BUF) * STG_B);                     \
            __half* Bsb = (__half*)(gsm + (BUF) * STG_B + ASTG_B);            \
            _Pragma("unroll")                                                 \
            for (int j = 0; j < 2; j++) {                                     \
                int idx = j * 256 + tid;                                      \
                int r = idx >> 2, c = idx & 3;                                \
                cpa16(smem_u32(&Asb[r * LDAH + c * 8]),                       \
                      A + (size_t)(row0 + r) * K + (KT) * 32 + c * 8);        \
            }                                                                 \
            _Pragma("unroll")                                                 \
            for (int j = 0; j < 2; j++) {                                     \
                int idx = j * 256 + tid;                                      \
                int kr = idx >> 4, c = idx & 15;                              \
                cpa16(smem_u32(&Bsb[kr * LDBH + c * 8]),                      \
                      W + (size_t)((KT) * 32 + kr) * N + col0 + c * 8);       \
            }                                                                 \
        } while (0)

    const int i = lane;
    const int a_lrow = wm * 32 + (i & 7) + ((i >> 3) & 1) * 8;
    const int a_lk   = ((i >> 4) & 1) * 8;
    const int b_lk   = (i & 7) + ((i >> 3) & 1) * 8;
    const int b_lc   = wn * 64 + ((i >> 4) & 1) * 8;
    const uint32_t a_off = (a_lrow * LDAH + a_lk) * 2;
    const uint32_t b_off = ASTG_B + (b_lk * LDBH + b_lc) * 2;
    const uint32_t smb = smem_u32(gsm);

    const int NT = K / 32;
    GSTAGE(0, 0);
    CP_COMMIT();
    GSTAGE(1, 1);
    CP_COMMIT();

    for (int t = 0; t < NT; t++) {
        if (t + 2 < NT) GSTAGE((t + 2) & 3, t + 2);
        CP_COMMIT();
        CP_WAIT(2);
        __syncthreads();

        const uint32_t bufb = smb + (t & 3) * STG_B;
        const uint32_t abase = bufb + a_off;
        const uint32_t bbase = bufb + b_off;
        #pragma unroll
        for (int ks = 0; ks < 2; ks++) {
            uint32_t af[2][4];
            ldsm_x4(af[0], abase + ks * 32);
            ldsm_x4(af[1], abase + 16 * LDAH * 2 + ks * 32);
            uint32_t bf[4][4];
            #pragma unroll
            for (int nb = 0; nb < 4; nb++)
                ldsm_x4t(bf[nb], bbase + (ks * 16 * LDBH + nb * 16) * 2);
            #pragma unroll
            for (int nb = 0; nb < 4; nb++)
                #pragma unroll
                for (int hn = 0; hn < 2; hn++) {
                    int ni = nb * 2 + hn;
                    mma_f16(acc[0][ni], af[0], bf[nb][hn * 2], bf[nb][hn * 2 + 1]);
                    mma_f16(acc[1][ni], af[1], bf[nb][hn * 2], bf[nb][hn * 2 + 1]);
                }
        }
    }

    float bx[8], by[8];
    #pragma unroll
    for (int ni = 0; ni < 8; ni++) {
        int c = col0 + wn * 64 + ni * 8 + 2 * tig;
        bx[ni] = __ldg(&bias[c]);
        by[ni] = __ldg(&bias[c + 1]);
    }
    #pragma unroll
    for (int mi = 0; mi < 2; mi++) {
        int r = row0 + wm * 32 + mi * 16 + gid;
        #pragma unroll
        for (int ni = 0; ni < 8; ni++) {
            int c = col0 + wn * 64 + ni * 8 + 2 * tig;
            if (OUT16) {
                __half* C16 = (__half*)Cout;
                __half2 h0 = __floats2half2_rn(acc[mi][ni][0] + bx[ni],
                                               acc[mi][ni][1] + by[ni]);
                __half2 h1 = __floats2half2_rn(acc[mi][ni][2] + bx[ni],
                                               acc[mi][ni][3] + by[ni]);
                *reinterpret_cast<__half2*>(&C16[(size_t)r * N + c]) = h0;
                *reinterpret_cast<__half2*>(&C16[(size_t)(r + 8) * N + c]) = h1;
            } else {
                float* C32 = (float*)Cout;
                float2 o0 = make_float2(acc[mi][ni][0] + bx[ni],
                                        acc[mi][ni][1] + by[ni]);
                float2 o1 = make_float2(acc[mi][ni][2] + bx[ni],
                                        acc[mi][ni][3] + by[ni]);
                *reinterpret_cast<float2*>(&C32[(size_t)r * N + c]) = o0;
                *reinterpret_cast<float2*>(&C32[(size_t)(r + 8) * N + c]) = o1;
            }
        }
    }
}

// ---------------------------------------------------------------------------
// fp16 flash attention v5: R14 v4 + hardware ex2.approx (MUFU) for all exps.
// 128 queries/CTA, 8 warps, 4-stage KV ring, ONE sync per tile,
// pre-scaled Q (scores arrive in log2 domain).
// ---------------------------------------------------------------------------
#define AST 72
#define Q_BYTES  (128 * AST * 2)
#define KV_BYTES (64 * AST * 2)
#define STAGE_B  (2 * KV_BYTES)
#define ASMEM_TOTAL (Q_BYTES + 4 * STAGE_B)

__global__ __launch_bounds__(256, 2)
void attn_f16_v5(const __half* __restrict__ qkv, __half* __restrict__ ctx)
{
    extern __shared__ char smraw[];
    __half* Qs = (__half*)smraw;

    const int h  = blockIdx.x;
    const int qt = gridDim.y - 1 - blockIdx.y;   // long CTAs first
    const int q0 = qt * 128;

    const int tid  = threadIdx.x;
    const int warp = tid >> 5;
    const int lane = tid & 31;
    const int gid  = lane >> 2;
    const int tig  = lane & 3;
    const int wr0  = warp * 16;

    #define ASTAGE(BUF, K0)                                                   \
        do {                                                                  \
            char* base = smraw + Q_BYTES + (BUF) * STAGE_B;                   \
            __half* Ksb = (__half*)base;                                      \
            __half* Vsb = (__half*)(base + KV_BYTES);                         \
            _Pragma("unroll")                                                 \
            for (int j = 0; j < 2; j++) {                                     \
                int idx = j * 256 + tid;                                      \
                int r = idx >> 3, c = idx & 7;                                \
                const __half* kp = qkv                                        \
                    + ((size_t)((K0) + r)) * (3 * DD)                         \
                    + DD + h * HDIM + c * 8;                                  \
                cpa16(smem_u32(&Ksb[r * AST + c * 8]), kp);                   \
                cpa16(smem_u32(&Vsb[r * AST + c * 8]), kp + DD);              \
            }                                                                 \
        } while (0)

    const int nt = q0 / 64 + 2;
    ASTAGE(0, 0);
    CP_COMMIT();
    ASTAGE(1, 64);
    CP_COMMIT();

    #pragma unroll
    for (int j = 0; j < 4; j++) {
        int idx = j * 256 + tid;
        int r = idx >> 3, c = idx & 7;
        uint4 v = *reinterpret_cast<const uint4*>(
            qkv + ((size_t)(q0 + r)) * (3 * DD) + h * HDIM + c * 8);
        *reinterpret_cast<uint4*>(&Qs[r * AST + c * 8]) = v;
    }
    __syncthreads();

    const int i = lane;
    uint32_t qa[4][4];
    {
        uint32_t qbase = smem_u32(
            &Qs[(wr0 + (i & 7) + ((i >> 3) & 1) * 8) * AST + ((i >> 4) & 1) * 8]);
        #pragma unroll
        for (int ks = 0; ks < 4; ks++) ldsm_x4(qa[ks], qbase + ks * 32);
    }

    const uint32_t kv0 = smem_u32(smraw + Q_BYTES);
    const uint32_t k_off = (((i & 7) + ((i >> 4) & 1) * 8) * AST
                            + ((i >> 3) & 1) * 8) * 2;
    const uint32_t v_off = KV_BYTES + (((i & 7) + ((i >> 3) & 1) * 8) * AST
                                       + ((i >> 4) & 1) * 8) * 2;

    float oacc[8][4];
    #pragma unroll
    for (int a = 0; a < 8; a++)
        #pragma unroll
        for (int v = 0; v < 4; v++) oacc[a][v] = 0.f;
    float m0 = -1e30f, m1 = -1e30f, l0 = 0.f, l1 = 0.f;

    const int warp_maxrow = q0 + wr0 + 15;
    for (int t = 0; t < nt; t++) {
        const int k0 = t * 64;
        if (t + 2 < nt) ASTAGE((t + 2) & 3, (t + 2) * 64);
        CP_COMMIT();
        CP_WAIT(2);
        __syncthreads();

        if (k0 <= warp_maxrow) {
            const uint32_t stageb = kv0 + (t & 3) * STAGE_B;
            const uint32_t kbase = stageb + k_off;
            const uint32_t vbase = stageb + v_off;

            float sacc[8][4];
            #pragma unroll
            for (int ni = 0; ni < 8; ni++)
                sacc[ni][0] = sacc[ni][1] = sacc[ni][2] = sacc[ni][3] = 0.f;
            #pragma unroll
            for (int ks = 0; ks < 4; ks++) {
                #pragma unroll
                for (int kt = 0; kt < 4; kt++) {
                    uint32_t kf[4];
                    ldsm_x4(kf, kbase + (kt * 16 * AST + ks * 16) * 2);
                    mma_f16(sacc[kt * 2 + 0], qa[ks], kf[0], kf[1]);
                    mma_f16(sacc[kt * 2 + 1], qa[ks], kf[2], kf[3]);
                }
            }

            const int rg0 = q0 + wr0 + gid;
            const bool need_mask = (k0 + 63 > q0 + wr0);
            if (need_mask) {
                #pragma unroll
                for (int ni = 0; ni < 8; ni++) {
                    int cg = k0 + ni * 8 + 2 * tig;
                    if (cg     > rg0)     sacc[ni][0] = -1e30f;
                    if (cg + 1 > rg0)     sacc[ni][1] = -1e30f;
                    if (cg     > rg0 + 8) sacc[ni][2] = -1e30f;
                    if (cg + 1 > rg0 + 8) sacc[ni][3] = -1e30f;
                }
            }

            float tmax0 = -1e30f, tmax1 = -1e30f;
            #pragma unroll
            for (int ni = 0; ni < 8; ni++) {
                tmax0 = fmaxf(tmax0, fmaxf(sacc[ni][0], sacc[ni][1]));
                tmax1 = fmaxf(tmax1, fmaxf(sacc[ni][2], sacc[ni][3]));
            }
            tmax0 = fmaxf(tmax0, __shfl_xor_sync(0xffffffffu, tmax0, 1));
            tmax0 = fmaxf(tmax0, __shfl_xor_sync(0xffffffffu, tmax0, 2));
            tmax1 = fmaxf(tmax1, __shfl_xor_sync(0xffffffffu, tmax1, 1));
            tmax1 = fmaxf(tmax1, __shfl_xor_sync(0xffffffffu, tmax1, 2));

            float mn0 = fmaxf(m0, tmax0);
            float mn1 = fmaxf(m1, tmax1);
            float c0 = ex2(m0 - mn0);
            float c1 = ex2(m1 - mn1);
            const bool renorm =
                __any_sync(0xffffffffu, (mn0 > m0) || (mn1 > m1));
            m0 = mn0; m1 = mn1;

            float s0 = 0.f, s1 = 0.f;
            #pragma unroll
            for (int ni = 0; ni < 8; ni++) {
                sacc[ni][0] = ex2(sacc[ni][0] - mn0);
                sacc[ni][1] = ex2(sacc[ni][1] - mn0);
                sacc[ni][2] = ex2(sacc[ni][2] - mn1);
                sacc[ni][3] = ex2(sacc[ni][3] - mn1);
                s0 += sacc[ni][0] + sacc[ni][1];
                s1 += sacc[ni][2] + sacc[ni][3];
            }
            if (renorm) {
                #pragma unroll
                for (int ni = 0; ni < 8; ni++) {
                    oacc[ni][0] *= c0; oacc[ni][1] *= c0;
                    oacc[ni][2] *= c1; oacc[ni][3] *= c1;
                }
            }
            s0 += __shfl_xor_sync(0xffffffffu, s0, 1);
            s0 += __shfl_xor_sync(0xffffffffu, s0, 2);
            s1 += __shfl_xor_sync(0xffffffffu, s1, 1);
            s1 += __shfl_xor_sync(0xffffffffu, s1, 2);
            l0 = l0 * c0 + s0;
            l1 = l1 * c1 + s1;

            #pragma unroll
            for (int s = 0; s < 4; s++) {
                uint32_t pa[4];
                pa[0] = h2bits(sacc[2 * s][0],     sacc[2 * s][1]);
                pa[1] = h2bits(sacc[2 * s][2],     sacc[2 * s][3]);
                pa[2] = h2bits(sacc[2 * s + 1][0], sacc[2 * s + 1][1]);
                pa[3] = h2bits(sacc[2 * s + 1][2], sacc[2 * s + 1][3]);
                #pragma unroll
                for (int db = 0; db < 4; db++) {
                    uint32_t vf[4];
                    ldsm_x4t(vf, vbase + (s * 16 * AST + db * 16) * 2);
                    mma_f16(oacc[db * 2 + 0], pa, vf[0], vf[1]);
                    mma_f16(oacc[db * 2 + 1], pa, vf[2], vf[3]);
                }
            }
        }
    }

    float inv0 = 1.f / l0;
    float inv1 = 1.f / l1;
    int row0 = q0 + wr0 + gid;
    int row1 = row0 + 8;
    #pragma unroll
    for (int ni = 0; ni < 8; ni++) {
        int d = h * HDIM + ni * 8 + 2 * tig;
        __half2 h0 = __floats2half2_rn(oacc[ni][0] * inv0, oacc[ni][1] * inv0);
        __half2 h1 = __floats2half2_rn(oacc[ni][2] * inv1, oacc[ni][3] * inv1);
        *reinterpret_cast<__half2*>(&ctx[((size_t)row0) * DD + d]) = h0;
        *reinterpret_cast<__half2*>(&ctx[((size_t)row1) * DD + d]) = h1;
    }
}

// ---------------------------------------------------------------------------
// Launch: per-batch fork-join pipeline over 4 streams (R12-proven footprint),
// with per-batch hidden conversion at chain heads and weights conversion
// overlapped on the main stream.
// ---------------------------------------------------------------------------
extern "C" void kernel_launch(void* const* d_in, const int* in_sizes, int n_in,
                              void* d_out, int out_size)
{
    const float* hidden = (const float*)d_in[0];
    const float* w_attn = (const float*)d_in[1];
    const float* b_attn = (const float*)d_in[2];
    const float* w_proj = (const float*)d_in[3];
    const float* b_proj = (const float*)d_in[4];
    float* out = (float*)d_out;

    __half *h16, *wa16, *wp16, *qkv16, *ctx16;
    float* ba;
    cudaGetSymbolAddress((void**)&h16,   g_h16);
    cudaGetSymbolAddress((void**)&wa16,  g_wa16);
    cudaGetSymbolAddress((void**)&wp16,  g_wp16);
    cudaGetSymbolAddress((void**)&qkv16, g_qkv16);
    cudaGetSymbolAddress((void**)&ctx16, g_ctx16);
    cudaGetSymbolAddress((void**)&ba,    g_ba);

    static cudaStream_t side[3];
    static cudaEvent_t ev_w, ev_done[3];
    static bool init_done = false;
    if (!init_done) {
        cudaFuncSetAttribute(gemm_f16_v5<1>,
                             cudaFuncAttributeMaxDynamicSharedMemorySize,
                             GSMEM_TOTAL);
        cudaFuncSetAttribute(gemm_f16_v5<0>,
                             cudaFuncAttributeMaxDynamicSharedMemorySize,
                             GSMEM_TOTAL);
        cudaFuncSetAttribute(attn_f16_v5,
                             cudaFuncAttributeMaxDynamicSharedMemorySize,
                             ASMEM_TOTAL);
        for (int s = 0; s < 3; s++) {
            cudaStreamCreateWithFlags(&side[s], cudaStreamNonBlocking);
            cudaEventCreateWithFlags(&ev_done[s], cudaEventDisableTiming);
        }
        cudaEventCreateWithFlags(&ev_w, cudaEventDisableTiming);
        init_done = true;
    }

    // 0) weights conversion on the main stream (chains overlap with this)
    conv_weights<<<1024, 256>>>((const float4*)w_attn, (const float4*)w_proj,
                                b_attn, (uint2*)wa16, (uint2*)wp16);
    cudaEventRecord(ev_w, 0);

    // per-batch chains: batch 0 on main stream, batches 1..3 on side streams
    for (int b = 0; b < BB; b++) {
        cudaStream_t st = (b == 0) ? (cudaStream_t)0 : side[b - 1];
        const size_t rowoff = (size_t)b * SS;
        const __half* hb   = h16   + rowoff * DD;
        __half*       qkvb = qkv16 + rowoff * 3 * DD;
        __half*       ctxb = ctx16 + rowoff * DD;
        float*        outb = out   + rowoff * DD;

        // hidden conversion for this batch (independent of weights)
        conv_hidden<<<512, 256, 0, st>>>(
            (const float4*)(hidden + rowoff * DD), (uint2*)(h16 + rowoff * DD));

        // QKV needs converted weights
        if (b != 0) cudaStreamWaitEvent(st, ev_w, 0);
        {
            dim3 grid(3 * DD / 128, SS / 128);
            gemm_f16_v5<1><<<grid, 256, GSMEM_TOTAL, st>>>(
                hb, wa16, ba, qkvb, SS, 3 * DD, DD);
        }
        {
            dim3 grid(HH, SS / 128);
            attn_f16_v5<<<grid, 256, ASMEM_TOTAL, st>>>(qkvb, ctxb);
        }
        {
            dim3 grid(DD / 128, SS / 128);
            gemm_f16_v5<0><<<grid, 256, GSMEM_TOTAL, st>>>(
                ctxb, wp16, b_proj, outb, SS, DD, DD);
        }
        if (b > 0) cudaEventRecord(ev_done[b - 1], st);
    }

    // join side streams back onto the main stream
    for (int s = 0; s < 3; s++)
        cudaStreamWaitEvent((cudaStream_t)0, ev_done[s], 0);
}

// round 17
// speedup vs baseline: 1.4998x; 1.4998x over previous
#include <cuda_runtime.h>
#include <cuda_fp16.h>
#include <math.h>
#include <stdint.h>

#define BB 4
#define SS 2048
#define DD 1024
#define HH 16
#define HDIM 64

#define SCALE_L2E 0.18033688011112042f   // 0.125 * log2(e)

// fp16 scratch (device globals: allocation-free per harness rules)
__device__ __half g_h16[BB * SS * DD];
__device__ __half g_wa16[DD * 3 * DD];    // Q-columns pre-scaled by SCALE_L2E
__device__ __half g_wp16[DD * DD];
__device__ __half g_qkv16[BB * SS * 3 * DD];
__device__ __half g_ctx16[BB * SS * DD];
__device__ float  g_ba[3 * DD];           // scaled copy of b_attn

// ---------------------------------------------------------------------------
// helpers
// ---------------------------------------------------------------------------
__device__ __forceinline__ uint32_t smem_u32(const void* p) {
    uint32_t a;
    asm("{ .reg .u64 t; cvta.to.shared.u64 t, %1; cvt.u32.u64 %0, t; }"
        : "=r"(a) : "l"(p));
    return a;
}

__device__ __forceinline__ void cpa16(uint32_t dst, const void* src) {
    asm volatile("cp.async.ca.shared.global [%0], [%1], 16;"
                 :: "r"(dst), "l"(src));
}
#define CP_COMMIT() asm volatile("cp.async.commit_group;")
#define CP_WAIT(n)  asm volatile("cp.async.wait_group %0;" :: "n"(n))

__device__ __forceinline__ void ldsm_x4(uint32_t* d, uint32_t addr) {
    asm volatile("ldmatrix.sync.aligned.m8n8.x4.shared.b16 {%0,%1,%2,%3}, [%4];"
                 : "=r"(d[0]), "=r"(d[1]), "=r"(d[2]), "=r"(d[3]) : "r"(addr));
}
__device__ __forceinline__ void ldsm_x4t(uint32_t* d, uint32_t addr) {
    asm volatile("ldmatrix.sync.aligned.m8n8.x4.trans.shared.b16 {%0,%1,%2,%3}, [%4];"
                 : "=r"(d[0]), "=r"(d[1]), "=r"(d[2]), "=r"(d[3]) : "r"(addr));
}

__device__ __forceinline__ void mma_f16(float* c, const uint32_t* a,
                                        uint32_t b0, uint32_t b1) {
    asm volatile(
        "mma.sync.aligned.m16n8k16.row.col.f32.f16.f16.f32 "
        "{%0,%1,%2,%3}, {%4,%5,%6,%7}, {%8,%9}, {%0,%1,%2,%3};"
        : "+f"(c[0]), "+f"(c[1]), "+f"(c[2]), "+f"(c[3])
        : "r"(a[0]), "r"(a[1]), "r"(a[2]), "r"(a[3]), "r"(b0), "r"(b1));
}

__device__ __forceinline__ uint32_t h2bits(float x, float y) {
    __half2 h = __floats2half2_rn(x, y);
    return *reinterpret_cast<uint32_t*>(&h);
}

// ---------------------------------------------------------------------------
// conversion kernels
// ---------------------------------------------------------------------------
#define N4_WA (DD * 3 * DD / 4)
#define N4_WP (DD * DD / 4)
#define N4_W  (N4_WA + N4_WP)
#define N4_HB (SS * DD / 4)     // one batch of hidden

__global__ void conv_weights(const float4* __restrict__ s_wa,
                             const float4* __restrict__ s_wp,
                             const float* __restrict__ b_attn,
                             uint2* __restrict__ d_wa,
                             uint2* __restrict__ d_wp)
{
    int i0 = blockIdx.x * blockDim.x + threadIdx.x;
    if (i0 < 3 * DD)
        g_ba[i0] = b_attn[i0] * ((i0 < DD) ? SCALE_L2E : 1.0f);

    const int stride = gridDim.x * blockDim.x;
    for (int i = i0; i < N4_W; i += stride) {
        if (i < N4_WA) {
            float4 v = s_wa[i];
            float s = (((i * 4) % (3 * DD)) < DD) ? SCALE_L2E : 1.0f;
            uint2 u;
            u.x = h2bits(v.x * s, v.y * s);
            u.y = h2bits(v.z * s, v.w * s);
            d_wa[i] = u;
        } else {
            int idx = i - N4_WA;
            float4 v = s_wp[idx];
            uint2 u;
            u.x = h2bits(v.x, v.y);
            u.y = h2bits(v.z, v.w);
            d_wp[idx] = u;
        }
    }
}

__global__ void conv_hidden(const float4* __restrict__ src,
                            uint2* __restrict__ dst)
{
    int i = blockIdx.x * blockDim.x + threadIdx.x;
    const int stride = gridDim.x * blockDim.x;
    for (; i < N4_HB; i += stride) {
        float4 v = src[i];
        uint2 u;
        u.x = h2bits(v.x, v.y);
        u.y = h2bits(v.z, v.w);
        dst[i] = u;
    }
}

// ---------------------------------------------------------------------------
// fp16 GEMM v5 (R11 winner): CTA 128x128, BK=32, 8 warps, warp 32x64,
// 4-stage cp.async ring, ONE __syncthreads per epoch.
// ---------------------------------------------------------------------------
#define LDAH 40
#define LDBH 136
#define ASTG_B (128 * LDAH * 2)
#define BSTG_B (32 * LDBH * 2)
#define STG_B  (ASTG_B + BSTG_B)
#define GSMEM_TOTAL (4 * STG_B)

template<int OUT16>
__global__ __launch_bounds__(256, 2)
void gemm_f16_v5(const __half* __restrict__ A, const __half* __restrict__ W,
                 const float* __restrict__ bias, void* __restrict__ Cout,
                 int M, int N, int K)
{
    extern __shared__ char gsm[];

    const int tid  = threadIdx.x;
    const int warp = tid >> 5;
    const int lane = tid & 31;
    const int gid  = lane >> 2;
    const int tig  = lane & 3;
    const int wm = warp >> 1;
    const int wn = warp & 1;

    const int row0 = blockIdx.y * 128;
    const int col0 = blockIdx.x * 128;

    float acc[2][8][4];
    #pragma unroll
    for (int a = 0; a < 2; a++)
        #pragma unroll
        for (int j = 0; j < 8; j++)
            #pragma unroll
            for (int v = 0; v < 4; v++) acc[a][j][v] = 0.f;

    #define GSTAGE(BUF, KT)                                                   \
        do {                                                                  \
            __half* Asb = (__half*)(gsm + (BUF) * STG_B);                     \
            __half* Bsb = (__half*)(gsm + (BUF) * STG_B + ASTG_B);            \
            _Pragma("unroll")                                                 \
            for (int j = 0; j < 2; j++) {                                     \
                int idx = j * 256 + tid;                                      \
                int r = idx >> 2, c = idx & 3;                                \
                cpa16(smem_u32(&Asb[r * LDAH + c * 8]),                       \
                      A + (size_t)(row0 + r) * K + (KT) * 32 + c * 8);        \
            }                                                                 \
            _Pragma("unroll")                                                 \
            for (int j = 0; j < 2; j++) {                                     \
                int idx = j * 256 + tid;                                      \
                int kr = idx >> 4, c = idx & 15;                              \
                cpa16(smem_u32(&Bsb[kr * LDBH + c * 8]),                      \
                      W + (size_t)((KT) * 32 + kr) * N + col0 + c * 8);       \
            }                                                                 \
        } while (0)

    const int i = lane;
    const int a_lrow = wm * 32 + (i & 7) + ((i >> 3) & 1) * 8;
    const int a_lk   = ((i >> 4) & 1) * 8;
    const int b_lk   = (i & 7) + ((i >> 3) & 1) * 8;
    const int b_lc   = wn * 64 + ((i >> 4) & 1) * 8;
    const uint32_t a_off = (a_lrow * LDAH + a_lk) * 2;
    const uint32_t b_off = ASTG_B + (b_lk * LDBH + b_lc) * 2;
    const uint32_t smb = smem_u32(gsm);

    const int NT = K / 32;
    GSTAGE(0, 0);
    CP_COMMIT();
    GSTAGE(1, 1);
    CP_COMMIT();

    for (int t = 0; t < NT; t++) {
        if (t + 2 < NT) GSTAGE((t + 2) & 3, t + 2);
        CP_COMMIT();
        CP_WAIT(2);
        __syncthreads();

        const uint32_t bufb = smb + (t & 3) * STG_B;
        const uint32_t abase = bufb + a_off;
        const uint32_t bbase = bufb + b_off;
        #pragma unroll
        for (int ks = 0; ks < 2; ks++) {
            uint32_t af[2][4];
            ldsm_x4(af[0], abase + ks * 32);
            ldsm_x4(af[1], abase + 16 * LDAH * 2 + ks * 32);
            uint32_t bf[4][4];
            #pragma unroll
            for (int nb = 0; nb < 4; nb++)
                ldsm_x4t(bf[nb], bbase + (ks * 16 * LDBH + nb * 16) * 2);
            #pragma unroll
            for (int nb = 0; nb < 4; nb++)
                #pragma unroll
                for (int hn = 0; hn < 2; hn++) {
                    int ni = nb * 2 + hn;
                    mma_f16(acc[0][ni], af[0], bf[nb][hn * 2], bf[nb][hn * 2 + 1]);
                    mma_f16(acc[1][ni], af[1], bf[nb][hn * 2], bf[nb][hn * 2 + 1]);
                }
        }
    }

    float bx[8], by[8];
    #pragma unroll
    for (int ni = 0; ni < 8; ni++) {
        int c = col0 + wn * 64 + ni * 8 + 2 * tig;
        bx[ni] = __ldg(&bias[c]);
        by[ni] = __ldg(&bias[c + 1]);
    }
    #pragma unroll
    for (int mi = 0; mi < 2; mi++) {
        int r = row0 + wm * 32 + mi * 16 + gid;
        #pragma unroll
        for (int ni = 0; ni < 8; ni++) {
            int c = col0 + wn * 64 + ni * 8 + 2 * tig;
            if (OUT16) {
                __half* C16 = (__half*)Cout;
                __half2 h0 = __floats2half2_rn(acc[mi][ni][0] + bx[ni],
                                               acc[mi][ni][1] + by[ni]);
                __half2 h1 = __floats2half2_rn(acc[mi][ni][2] + bx[ni],
                                               acc[mi][ni][3] + by[ni]);
                *reinterpret_cast<__half2*>(&C16[(size_t)r * N + c]) = h0;
                *reinterpret_cast<__half2*>(&C16[(size_t)(r + 8) * N + c]) = h1;
            } else {
                float* C32 = (float*)Cout;
                float2 o0 = make_float2(acc[mi][ni][0] + bx[ni],
                                        acc[mi][ni][1] + by[ni]);
                float2 o1 = make_float2(acc[mi][ni][2] + bx[ni],
                                        acc[mi][ni][3] + by[ni]);
                *reinterpret_cast<float2*>(&C32[(size_t)r * N + c]) = o0;
                *reinterpret_cast<float2*>(&C32[(size_t)(r + 8) * N + c]) = o1;
            }
        }
    }
}

// ---------------------------------------------------------------------------
// fp16 flash attention v4 (R14 winner): 128 queries/CTA, 8 warps,
// 4-stage KV ring, ONE sync per tile, pre-scaled Q (log2 domain),
// compiler-scheduled exp2f (fast-math lowers to MUFU with full ILP).
// ---------------------------------------------------------------------------
#define AST 72
#define Q_BYTES  (128 * AST * 2)
#define KV_BYTES (64 * AST * 2)
#define STAGE_B  (2 * KV_BYTES)
#define ASMEM_TOTAL (Q_BYTES + 4 * STAGE_B)

__global__ __launch_bounds__(256, 2)
void attn_f16_v4(const __half* __restrict__ qkv, __half* __restrict__ ctx)
{
    extern __shared__ char smraw[];
    __half* Qs = (__half*)smraw;

    const int h  = blockIdx.x;
    const int qt = gridDim.y - 1 - blockIdx.y;   // long CTAs first
    const int q0 = qt * 128;

    const int tid  = threadIdx.x;
    const int warp = tid >> 5;
    const int lane = tid & 31;
    const int gid  = lane >> 2;
    const int tig  = lane & 3;
    const int wr0  = warp * 16;

    #define ASTAGE(BUF, K0)                                                   \
        do {                                                                  \
            char* base = smraw + Q_BYTES + (BUF) * STAGE_B;                   \
            __half* Ksb = (__half*)base;                                      \
            __half* Vsb = (__half*)(base + KV_BYTES);                         \
            _Pragma("unroll")                                                 \
            for (int j = 0; j < 2; j++) {                                     \
                int idx = j * 256 + tid;                                      \
                int r = idx >> 3, c = idx & 7;                                \
                const __half* kp = qkv                                        \
                    + ((size_t)((K0) + r)) * (3 * DD)                         \
                    + DD + h * HDIM + c * 8;                                  \
                cpa16(smem_u32(&Ksb[r * AST + c * 8]), kp);                   \
                cpa16(smem_u32(&Vsb[r * AST + c * 8]), kp + DD);              \
            }                                                                 \
        } while (0)

    const int nt = q0 / 64 + 2;
    ASTAGE(0, 0);
    CP_COMMIT();
    ASTAGE(1, 64);
    CP_COMMIT();

    #pragma unroll
    for (int j = 0; j < 4; j++) {
        int idx = j * 256 + tid;
        int r = idx >> 3, c = idx & 7;
        uint4 v = *reinterpret_cast<const uint4*>(
            qkv + ((size_t)(q0 + r)) * (3 * DD) + h * HDIM + c * 8);
        *reinterpret_cast<uint4*>(&Qs[r * AST + c * 8]) = v;
    }
    __syncthreads();

    const int i = lane;
    uint32_t qa[4][4];
    {
        uint32_t qbase = smem_u32(
            &Qs[(wr0 + (i & 7) + ((i >> 3) & 1) * 8) * AST + ((i >> 4) & 1) * 8]);
        #pragma unroll
        for (int ks = 0; ks < 4; ks++) ldsm_x4(qa[ks], qbase + ks * 32);
    }

    const uint32_t kv0 = smem_u32(smraw + Q_BYTES);
    const uint32_t k_off = (((i & 7) + ((i >> 4) & 1) * 8) * AST
                            + ((i >> 3) & 1) * 8) * 2;
    const uint32_t v_off = KV_BYTES + (((i & 7) + ((i >> 3) & 1) * 8) * AST
                                       + ((i >> 4) & 1) * 8) * 2;

    float oacc[8][4];
    #pragma unroll
    for (int a = 0; a < 8; a++)
        #pragma unroll
        for (int v = 0; v < 4; v++) oacc[a][v] = 0.f;
    float m0 = -1e30f, m1 = -1e30f, l0 = 0.f, l1 = 0.f;

    const int warp_maxrow = q0 + wr0 + 15;
    for (int t = 0; t < nt; t++) {
        const int k0 = t * 64;
        if (t + 2 < nt) ASTAGE((t + 2) & 3, (t + 2) * 64);
        CP_COMMIT();
        CP_WAIT(2);
        __syncthreads();

        if (k0 <= warp_maxrow) {
            const uint32_t stageb = kv0 + (t & 3) * STAGE_B;
            const uint32_t kbase = stageb + k_off;
            const uint32_t vbase = stageb + v_off;

            float sacc[8][4];
            #pragma unroll
            for (int ni = 0; ni < 8; ni++)
                sacc[ni][0] = sacc[ni][1] = sacc[ni][2] = sacc[ni][3] = 0.f;
            #pragma unroll
            for (int ks = 0; ks < 4; ks++) {
                #pragma unroll
                for (int kt = 0; kt < 4; kt++) {
                    uint32_t kf[4];
                    ldsm_x4(kf, kbase + (kt * 16 * AST + ks * 16) * 2);
                    mma_f16(sacc[kt * 2 + 0], qa[ks], kf[0], kf[1]);
                    mma_f16(sacc[kt * 2 + 1], qa[ks], kf[2], kf[3]);
                }
            }

            const int rg0 = q0 + wr0 + gid;
            const bool need_mask = (k0 + 63 > q0 + wr0);
            if (need_mask) {
                #pragma unroll
                for (int ni = 0; ni < 8; ni++) {
                    int cg = k0 + ni * 8 + 2 * tig;
                    if (cg     > rg0)     sacc[ni][0] = -1e30f;
                    if (cg + 1 > rg0)     sacc[ni][1] = -1e30f;
                    if (cg     > rg0 + 8) sacc[ni][2] = -1e30f;
                    if (cg + 1 > rg0 + 8) sacc[ni][3] = -1e30f;
                }
            }

            float tmax0 = -1e30f, tmax1 = -1e30f;
            #pragma unroll
            for (int ni = 0; ni < 8; ni++) {
                tmax0 = fmaxf(tmax0, fmaxf(sacc[ni][0], sacc[ni][1]));
                tmax1 = fmaxf(tmax1, fmaxf(sacc[ni][2], sacc[ni][3]));
            }
            tmax0 = fmaxf(tmax0, __shfl_xor_sync(0xffffffffu, tmax0, 1));
            tmax0 = fmaxf(tmax0, __shfl_xor_sync(0xffffffffu, tmax0, 2));
            tmax1 = fmaxf(tmax1, __shfl_xor_sync(0xffffffffu, tmax1, 1));
            tmax1 = fmaxf(tmax1, __shfl_xor_sync(0xffffffffu, tmax1, 2));

            float mn0 = fmaxf(m0, tmax0);
            float mn1 = fmaxf(m1, tmax1);
            float c0 = exp2f(m0 - mn0);
            float c1 = exp2f(m1 - mn1);
            const bool renorm =
                __any_sync(0xffffffffu, (mn0 > m0) || (mn1 > m1));
            m0 = mn0; m1 = mn1;

            float s0 = 0.f, s1 = 0.f;
            #pragma unroll
            for (int ni = 0; ni < 8; ni++) {
                sacc[ni][0] = exp2f(sacc[ni][0] - mn0);
                sacc[ni][1] = exp2f(sacc[ni][1] - mn0);
                sacc[ni][2] = exp2f(sacc[ni][2] - mn1);
                sacc[ni][3] = exp2f(sacc[ni][3] - mn1);
                s0 += sacc[ni][0] + sacc[ni][1];
                s1 += sacc[ni][2] + sacc[ni][3];
            }
            if (renorm) {
                #pragma unroll
                for (int ni = 0; ni < 8; ni++) {
                    oacc[ni][0] *= c0; oacc[ni][1] *= c0;
                    oacc[ni][2] *= c1; oacc[ni][3] *= c1;
                }
            }
            s0 += __shfl_xor_sync(0xffffffffu, s0, 1);
            s0 += __shfl_xor_sync(0xffffffffu, s0, 2);
            s1 += __shfl_xor_sync(0xffffffffu, s1, 1);
            s1 += __shfl_xor_sync(0xffffffffu, s1, 2);
            l0 = l0 * c0 + s0;
            l1 = l1 * c1 + s1;

            #pragma unroll
            for (int s = 0; s < 4; s++) {
                uint32_t pa[4];
                pa[0] = h2bits(sacc[2 * s][0],     sacc[2 * s][1]);
                pa[1] = h2bits(sacc[2 * s][2],     sacc[2 * s][3]);
                pa[2] = h2bits(sacc[2 * s + 1][0], sacc[2 * s + 1][1]);
                pa[3] = h2bits(sacc[2 * s + 1][2], sacc[2 * s + 1][3]);
                #pragma unroll
                for (int db = 0; db < 4; db++) {
                    uint32_t vf[4];
                    ldsm_x4t(vf, vbase + (s * 16 * AST + db * 16) * 2);
                    mma_f16(oacc[db * 2 + 0], pa, vf[0], vf[1]);
                    mma_f16(oacc[db * 2 + 1], pa, vf[2], vf[3]);
                }
            }
        }
    }

    float inv0 = 1.f / l0;
    float inv1 = 1.f / l1;
    int row0 = q0 + wr0 + gid;
    int row1 = row0 + 8;
    #pragma unroll
    for (int ni = 0; ni < 8; ni++) {
        int d = h * HDIM + ni * 8 + 2 * tig;
        __half2 h0 = __floats2half2_rn(oacc[ni][0] * inv0, oacc[ni][1] * inv0);
        __half2 h1 = __floats2half2_rn(oacc[ni][2] * inv1, oacc[ni][3] * inv1);
        *reinterpret_cast<__half2*>(&ctx[((size_t)row0) * DD + d]) = h0;
        *reinterpret_cast<__half2*>(&ctx[((size_t)row1) * DD + d]) = h1;
    }
}

// ---------------------------------------------------------------------------
// Launch: per-batch fork-join pipeline over 4 streams (R12-proven footprint),
// per-batch hidden conversion at chain heads, weights conversion overlapped.
// ---------------------------------------------------------------------------
extern "C" void kernel_launch(void* const* d_in, const int* in_sizes, int n_in,
                              void* d_out, int out_size)
{
    const float* hidden = (const float*)d_in[0];
    const float* w_attn = (const float*)d_in[1];
    const float* b_attn = (const float*)d_in[2];
    const float* w_proj = (const float*)d_in[3];
    const float* b_proj = (const float*)d_in[4];
    float* out = (float*)d_out;

    __half *h16, *wa16, *wp16, *qkv16, *ctx16;
    float* ba;
    cudaGetSymbolAddress((void**)&h16,   g_h16);
    cudaGetSymbolAddress((void**)&wa16,  g_wa16);
    cudaGetSymbolAddress((void**)&wp16,  g_wp16);
    cudaGetSymbolAddress((void**)&qkv16, g_qkv16);
    cudaGetSymbolAddress((void**)&ctx16, g_ctx16);
    cudaGetSymbolAddress((void**)&ba,    g_ba);

    static cudaStream_t side[3];
    static cudaEvent_t ev_w, ev_done[3];
    static bool init_done = false;
    if (!init_done) {
        cudaFuncSetAttribute(gemm_f16_v5<1>,
                             cudaFuncAttributeMaxDynamicSharedMemorySize,
                             GSMEM_TOTAL);
        cudaFuncSetAttribute(gemm_f16_v5<0>,
                             cudaFuncAttributeMaxDynamicSharedMemorySize,
                             GSMEM_TOTAL);
        cudaFuncSetAttribute(attn_f16_v4,
                             cudaFuncAttributeMaxDynamicSharedMemorySize,
                             ASMEM_TOTAL);
        for (int s = 0; s < 3; s++) {
            cudaStreamCreateWithFlags(&side[s], cudaStreamNonBlocking);
            cudaEventCreateWithFlags(&ev_done[s], cudaEventDisableTiming);
        }
        cudaEventCreateWithFlags(&ev_w, cudaEventDisableTiming);
        init_done = true;
    }

    // 0) weights conversion on the main stream (chains overlap with this)
    conv_weights<<<1024, 256>>>((const float4*)w_attn, (const float4*)w_proj,
                                b_attn, (uint2*)wa16, (uint2*)wp16);
    cudaEventRecord(ev_w, 0);

    // per-batch chains: batch 0 on main stream, batches 1..3 on side streams
    for (int b = 0; b < BB; b++) {
        cudaStream_t st = (b == 0) ? (cudaStream_t)0 : side[b - 1];
        const size_t rowoff = (size_t)b * SS;
        const __half* hb   = h16   + rowoff * DD;
        __half*       qkvb = qkv16 + rowoff * 3 * DD;
        __half*       ctxb = ctx16 + rowoff * DD;
        float*        outb = out   + rowoff * DD;

        // hidden conversion for this batch (independent of weights)
        conv_hidden<<<512, 256, 0, st>>>(
            (const float4*)(hidden + rowoff * DD), (uint2*)(h16 + rowoff * DD));

        // QKV needs converted weights
        if (b != 0) cudaStreamWaitEvent(st, ev_w, 0);
        {
            dim3 grid(3 * DD / 128, SS / 128);
            gemm_f16_v5<1><<<grid, 256, GSMEM_TOTAL, st>>>(
                hb, wa16, ba, qkvb, SS, 3 * DD, DD);
        }
        {
            dim3 grid(HH, SS / 128);
            attn_f16_v4<<<grid, 256, ASMEM_TOTAL, st>>>(qkvb, ctxb);
        }
        {
            dim3 grid(DD / 128, SS / 128);
            gemm_f16_v5<0><<<grid, 256, GSMEM_TOTAL, st>>>(
                ctxb, wp16, b_proj, outb, SS, DD, DD);
        }
        if (b > 0) cudaEventRecord(ev_done[b - 1], st);
    }

    // join side streams back onto the main stream
    for (int s = 0; s < 3; s++)
        cudaStreamWaitEvent((cudaStream_t)0, ev_done[s], 0);
}